// round 1
// baseline (speedup 1.0000x reference)
#include <cuda_runtime.h>
#include <cstdint>

#define T_STEPS 336
#define BATCH   4096
#define NFEAT   32
#define UN1     64
#define UN2     32
#define G1      256   // 4*UN1
#define G2      128   // 4*UN2
#define ROWS    32
#define THREADS 256
#define CTAS    (BATCH / ROWS)   // 128

// ---- shared memory layout (float offsets) ----
#define OFF_W1  0
#define OFF_U1  (OFF_W1 + NFEAT * G1)        // 8192
#define OFF_W2  (OFF_U1 + UN1 * G1)          // 24576
#define OFF_U2  (OFF_W2 + UN1 * G2)          // 32768
#define OFF_B1  (OFF_U2 + UN2 * G2)          // 36864
#define OFF_B2  (OFF_B1 + G1)                // 37120
#define OFF_H1  (OFF_B2 + G2)                // 37248
#define OFF_H2  (OFF_H1 + ROWS * UN1)        // 39296
#define OFF_X   (OFF_H2 + ROWS * UN2)        // 40320
#define SMEM_FLOATS (OFF_X + 2 * ROWS * NFEAT) // 42368 -> 169472 bytes

// ---------------- packed f32x2 helpers ----------------
__device__ __forceinline__ unsigned long long pack2(float a) {
    unsigned long long r;
    asm("mov.b64 %0, {%1, %1};" : "=l"(r) : "f"(a));
    return r;
}
__device__ __forceinline__ unsigned long long fma2(unsigned long long a,
                                                   unsigned long long b,
                                                   unsigned long long c) {
    unsigned long long d;
    asm("fma.rn.f32x2 %0, %1, %2, %3;" : "=l"(d) : "l"(a), "l"(b), "l"(c));
    return d;
}
__device__ __forceinline__ float2 unpack2(unsigned long long v) {
    float2 r;
    asm("mov.b64 {%0, %1}, %2;" : "=f"(r.x), "=f"(r.y) : "l"(v));
    return r;
}

// ---------------- activations (fast HW exp/rcp, ~1e-6 err) ----------------
__device__ __forceinline__ float sigm(float x) {
    float e = __expf(-x);
    return __fdividef(1.0f, 1.0f + e);
}
__device__ __forceinline__ float tanh_(float x) {
    float ax = fabsf(x);
    float e  = __expf(-2.0f * ax);          // in (0,1], no overflow
    float r  = __fdividef(1.0f - e, 1.0f + e);
    return copysignf(r, x);
}

// ---------------- cp.async helpers ----------------
__device__ __forceinline__ void cp16(uint32_t saddr, const float* g) {
    asm volatile("cp.async.cg.shared.global [%0], [%1], 16;" :: "r"(saddr), "l"(g));
}
__device__ __forceinline__ void cp_commit() {
    asm volatile("cp.async.commit_group;");
}
__device__ __forceinline__ void cp_wait1() {
    asm volatile("cp.async.wait_group 1;" ::: "memory");
}
__device__ __forceinline__ void cp_wait0() {
    asm volatile("cp.async.wait_group 0;" ::: "memory");
}

// One k-slice of the gate GEMM: 4 rows (h0..h3 broadcasts) x 8 gate columns
// (unit-pair x 4 gates, gate stride GS floats inside a weight row).
template <int GS>
__device__ __forceinline__ void mma_step(unsigned long long (&acc)[4][4],
                                         float h0, float h1, float h2, float h3,
                                         const float* __restrict__ wr) {
    unsigned long long w0 = *(const unsigned long long*)(wr);
    unsigned long long w1 = *(const unsigned long long*)(wr + GS);
    unsigned long long w2 = *(const unsigned long long*)(wr + 2 * GS);
    unsigned long long w3 = *(const unsigned long long*)(wr + 3 * GS);
    unsigned long long p;
    p = pack2(h0);
    acc[0][0] = fma2(p, w0, acc[0][0]); acc[0][1] = fma2(p, w1, acc[0][1]);
    acc[0][2] = fma2(p, w2, acc[0][2]); acc[0][3] = fma2(p, w3, acc[0][3]);
    p = pack2(h1);
    acc[1][0] = fma2(p, w0, acc[1][0]); acc[1][1] = fma2(p, w1, acc[1][1]);
    acc[1][2] = fma2(p, w2, acc[1][2]); acc[1][3] = fma2(p, w3, acc[1][3]);
    p = pack2(h2);
    acc[2][0] = fma2(p, w0, acc[2][0]); acc[2][1] = fma2(p, w1, acc[2][1]);
    acc[2][2] = fma2(p, w2, acc[2][2]); acc[2][3] = fma2(p, w3, acc[2][3]);
    p = pack2(h3);
    acc[3][0] = fma2(p, w0, acc[3][0]); acc[3][1] = fma2(p, w1, acc[3][1]);
    acc[3][2] = fma2(p, w2, acc[3][2]); acc[3][3] = fma2(p, w3, acc[3][3]);
}

__global__ void __launch_bounds__(THREADS, 1)
lstm_fused_kernel(const float* __restrict__ x,
                  const float* __restrict__ W1, const float* __restrict__ U1w, const float* __restrict__ b1,
                  const float* __restrict__ W2, const float* __restrict__ U2w, const float* __restrict__ b2,
                  const float* __restrict__ Wv, const float* __restrict__ bv,
                  const float* __restrict__ Wo, const float* __restrict__ bo,
                  const float* __restrict__ Wd1, const float* __restrict__ bd1,
                  const float* __restrict__ Wd2, const float* __restrict__ bd2,
                  float* __restrict__ out) {
    extern __shared__ float sm[];
    const int tid = threadIdx.x;
    const int b0  = blockIdx.x * ROWS;

    // ---- stage weights into SMEM (one time) ----
    for (int i = tid; i < (NFEAT * G1) / 4; i += THREADS)
        ((float4*)(sm + OFF_W1))[i] = ((const float4*)W1)[i];
    for (int i = tid; i < (UN1 * G1) / 4; i += THREADS)
        ((float4*)(sm + OFF_U1))[i] = ((const float4*)U1w)[i];
    for (int i = tid; i < (UN1 * G2) / 4; i += THREADS)
        ((float4*)(sm + OFF_W2))[i] = ((const float4*)W2)[i];
    for (int i = tid; i < (UN2 * G2) / 4; i += THREADS)
        ((float4*)(sm + OFF_U2))[i] = ((const float4*)U2w)[i];
    for (int i = tid; i < G1; i += THREADS) sm[OFF_B1 + i] = b1[i];
    for (int i = tid; i < G2; i += THREADS) sm[OFF_B2 + i] = b2[i];
    for (int i = tid; i < ROWS * UN1; i += THREADS) sm[OFF_H1 + i] = 0.0f;
    for (int i = tid; i < ROWS * UN2; i += THREADS) sm[OFF_H2 + i] = 0.0f;

    // LSTM1 mapping: 8 row-groups x 32 unit-pairs
    const int up = tid & 31;   // unit pair -> units 2*up, 2*up+1
    const int rg = tid >> 5;   // rows rg*4 .. rg*4+3
    // LSTM2 mapping (tid < 128): 8 row-groups x 16 unit-pairs
    const int up2 = tid & 15;
    const int rg2 = tid >> 4;

    float c1[4][2], c2[4][2];
#pragma unroll
    for (int r = 0; r < 4; r++) {
        c1[r][0] = c1[r][1] = 0.0f;
        c2[r][0] = c2[r][1] = 0.0f;
    }

    // ---- x prefetch mapping: one float4 per thread per step ----
    const int xrow = tid >> 3;   // 0..31
    const int xq   = tid & 7;    // 0..7
    const float* xg = x + ((size_t)(b0 + xrow) * T_STEPS) * NFEAT + xq * 4;
    uint32_t sx0 = (uint32_t)__cvta_generic_to_shared(sm + OFF_X + xrow * NFEAT + xq * 4);
    uint32_t sx1 = sx0 + ROWS * NFEAT * 4;   // byte offset of buffer 1

    cp16(sx0, xg);   // prefetch t = 0 into buffer 0
    cp_commit();

    __syncthreads();   // weights + zero state visible

    for (int t = 0; t < T_STEPS; ++t) {
        if (t + 1 < T_STEPS) {
            cp16((t & 1) ? sx0 : sx1, xg + (size_t)(t + 1) * NFEAT);
            cp_commit();
            cp_wait1();          // tile t complete (t+1 may be in flight)
        } else {
            cp_wait0();
        }
        __syncthreads();         // sync1: x_t visible; prev-step h2 writes visible

        const float* xb = sm + OFF_X + ((t & 1) ? ROWS * NFEAT : 0);

        // ================= LSTM layer 1 gates =================
        unsigned long long acc[4][4];
#pragma unroll
        for (int g = 0; g < 4; g++) {
            unsigned long long bsv = *(const unsigned long long*)(sm + OFF_B1 + g * UN1 + 2 * up);
#pragma unroll
            for (int r = 0; r < 4; r++) acc[r][g] = bsv;
        }
        // x contribution: K = 32
        {
            const float* r0 = xb + (rg * 4 + 0) * NFEAT;
            const float* r1 = xb + (rg * 4 + 1) * NFEAT;
            const float* r2 = xb + (rg * 4 + 2) * NFEAT;
            const float* r3 = xb + (rg * 4 + 3) * NFEAT;
#pragma unroll 1
            for (int k = 0; k < NFEAT; k += 4) {
                float4 a0 = *(const float4*)(r0 + k);
                float4 a1 = *(const float4*)(r1 + k);
                float4 a2 = *(const float4*)(r2 + k);
                float4 a3 = *(const float4*)(r3 + k);
                const float* w = sm + OFF_W1 + k * G1 + 2 * up;
                mma_step<UN1>(acc, a0.x, a1.x, a2.x, a3.x, w);
                mma_step<UN1>(acc, a0.y, a1.y, a2.y, a3.y, w + G1);
                mma_step<UN1>(acc, a0.z, a1.z, a2.z, a3.z, w + 2 * G1);
                mma_step<UN1>(acc, a0.w, a1.w, a2.w, a3.w, w + 3 * G1);
            }
        }
        // recurrent contribution: K = 64
        {
            const float* r0 = sm + OFF_H1 + (rg * 4 + 0) * UN1;
            const float* r1 = sm + OFF_H1 + (rg * 4 + 1) * UN1;
            const float* r2 = sm + OFF_H1 + (rg * 4 + 2) * UN1;
            const float* r3 = sm + OFF_H1 + (rg * 4 + 3) * UN1;
#pragma unroll 1
            for (int k = 0; k < UN1; k += 4) {
                float4 a0 = *(const float4*)(r0 + k);
                float4 a1 = *(const float4*)(r1 + k);
                float4 a2 = *(const float4*)(r2 + k);
                float4 a3 = *(const float4*)(r3 + k);
                const float* w = sm + OFF_U1 + k * G1 + 2 * up;
                mma_step<UN1>(acc, a0.x, a1.x, a2.x, a3.x, w);
                mma_step<UN1>(acc, a0.y, a1.y, a2.y, a3.y, w + G1);
                mma_step<UN1>(acc, a0.z, a1.z, a2.z, a3.z, w + 2 * G1);
                mma_step<UN1>(acc, a0.w, a1.w, a2.w, a3.w, w + 3 * G1);
            }
        }
        __syncthreads();   // sync2: all reads of h1_{t-1} done

        // c/h update (i, f, g, o); Keras gate order i,f,c,o
#pragma unroll
        for (int r = 0; r < 4; r++) {
            float2 zi = unpack2(acc[r][0]);
            float2 zf = unpack2(acc[r][1]);
            float2 zg = unpack2(acc[r][2]);
            float2 zo = unpack2(acc[r][3]);
            float i0 = sigm(zi.x), f0 = sigm(zf.x), g0 = tanh_(zg.x), o0 = sigm(zo.x);
            float i1 = sigm(zi.y), f1 = sigm(zf.y), g1 = tanh_(zg.y), o1 = sigm(zo.y);
            c1[r][0] = f0 * c1[r][0] + i0 * g0;
            c1[r][1] = f1 * c1[r][1] + i1 * g1;
            float2 h;
            h.x = o0 * tanh_(c1[r][0]);
            h.y = o1 * tanh_(c1[r][1]);
            *(float2*)(sm + OFF_H1 + (rg * 4 + r) * UN1 + 2 * up) = h;
        }
        __syncthreads();   // sync3: h1_t visible

        // ================= LSTM layer 2 gates (threads 0..127) =================
        unsigned long long acc2[4][4];
        if (tid < 128) {
#pragma unroll
            for (int g = 0; g < 4; g++) {
                unsigned long long bsv = *(const unsigned long long*)(sm + OFF_B2 + g * UN2 + 2 * up2);
#pragma unroll
                for (int r = 0; r < 4; r++) acc2[r][g] = bsv;
            }
            // input contribution from h1_t: K = 64
            {
                const float* r0 = sm + OFF_H1 + (rg2 * 4 + 0) * UN1;
                const float* r1 = sm + OFF_H1 + (rg2 * 4 + 1) * UN1;
                const float* r2 = sm + OFF_H1 + (rg2 * 4 + 2) * UN1;
                const float* r3 = sm + OFF_H1 + (rg2 * 4 + 3) * UN1;
#pragma unroll 1
                for (int k = 0; k < UN1; k += 4) {
                    float4 a0 = *(const float4*)(r0 + k);
                    float4 a1 = *(const float4*)(r1 + k);
                    float4 a2 = *(const float4*)(r2 + k);
                    float4 a3 = *(const float4*)(r3 + k);
                    const float* w = sm + OFF_W2 + k * G2 + 2 * up2;
                    mma_step<UN2>(acc2, a0.x, a1.x, a2.x, a3.x, w);
                    mma_step<UN2>(acc2, a0.y, a1.y, a2.y, a3.y, w + G2);
                    mma_step<UN2>(acc2, a0.z, a1.z, a2.z, a3.z, w + 2 * G2);
                    mma_step<UN2>(acc2, a0.w, a1.w, a2.w, a3.w, w + 3 * G2);
                }
            }
            // recurrent contribution from h2_{t-1}: K = 32
            {
                const float* r0 = sm + OFF_H2 + (rg2 * 4 + 0) * UN2;
                const float* r1 = sm + OFF_H2 + (rg2 * 4 + 1) * UN2;
                const float* r2 = sm + OFF_H2 + (rg2 * 4 + 2) * UN2;
                const float* r3 = sm + OFF_H2 + (rg2 * 4 + 3) * UN2;
#pragma unroll 1
                for (int k = 0; k < UN2; k += 4) {
                    float4 a0 = *(const float4*)(r0 + k);
                    float4 a1 = *(const float4*)(r1 + k);
                    float4 a2 = *(const float4*)(r2 + k);
                    float4 a3 = *(const float4*)(r3 + k);
                    const float* w = sm + OFF_U2 + k * G2 + 2 * up2;
                    mma_step<UN2>(acc2, a0.x, a1.x, a2.x, a3.x, w);
                    mma_step<UN2>(acc2, a0.y, a1.y, a2.y, a3.y, w + G2);
                    mma_step<UN2>(acc2, a0.z, a1.z, a2.z, a3.z, w + 2 * G2);
                    mma_step<UN2>(acc2, a0.w, a1.w, a2.w, a3.w, w + 3 * G2);
                }
            }
        }
        __syncthreads();   // sync4: all reads of h2_{t-1} done (all threads)

        if (tid < 128) {
#pragma unroll
            for (int r = 0; r < 4; r++) {
                float2 zi = unpack2(acc2[r][0]);
                float2 zf = unpack2(acc2[r][1]);
                float2 zg = unpack2(acc2[r][2]);
                float2 zo = unpack2(acc2[r][3]);
                float i0 = sigm(zi.x), f0 = sigm(zf.x), g0 = tanh_(zg.x), o0 = sigm(zo.x);
                float i1 = sigm(zi.y), f1 = sigm(zf.y), g1 = tanh_(zg.y), o1 = sigm(zo.y);
                c2[r][0] = f0 * c2[r][0] + i0 * g0;
                c2[r][1] = f1 * c2[r][1] + i1 * g1;
                float2 h;
                h.x = o0 * tanh_(c2[r][0]);
                h.y = o1 * tanh_(c2[r][1]);
                *(float2*)(sm + OFF_H2 + (rg2 * 4 + r) * UN2 + 2 * up2) = h;
            }
        }
        // next iteration's sync1 publishes h2_t
    }
    __syncthreads();

    // ================= head: MHA(seq=1) is identity-attention -> v@Wo, then MLP =================
    // v = h2 @ Wv + bv   (32x32), scratch in x-buffer region
    float* sv = sm + OFF_X;
    for (int idx = tid; idx < ROWS * 32; idx += THREADS) {
        int r = idx >> 5, j = idx & 31;
        float s = bv[j];
        const float* h2r = sm + OFF_H2 + r * UN2;
#pragma unroll
        for (int d = 0; d < 32; d++) s += h2r[d] * Wv[d * 32 + j];
        sv[idx] = s;
    }
    __syncthreads();
    // o = v @ Wo + bo   (32x32), scratch in h1 region
    float* so = sm + OFF_H1;
    for (int idx = tid; idx < ROWS * 32; idx += THREADS) {
        int r = idx >> 5, e = idx & 31;
        float s = bo[e];
#pragma unroll
        for (int j = 0; j < 32; j++) s += sv[r * 32 + j] * Wo[j * 32 + e];
        so[idx] = s;
    }
    __syncthreads();
    // d1 = relu(o @ Wd1 + bd1)   (32x64), reuse x-buffer
    float* sd1 = sm + OFF_X;
    for (int idx = tid; idx < ROWS * 64; idx += THREADS) {
        int r = idx >> 6, m = idx & 63;
        float s = bd1[m];
#pragma unroll
        for (int e = 0; e < 32; e++) s += so[r * 32 + e] * Wd1[e * 64 + m];
        sd1[idx] = fmaxf(s, 0.0f);
    }
    __syncthreads();
    // out = d1 @ Wd2 + bd2   (32x24) -> GMEM
    for (int idx = tid; idx < ROWS * 24; idx += THREADS) {
        int r = idx / 24, p = idx % 24;
        float s = bd2[p];
#pragma unroll
        for (int m = 0; m < 64; m++) s += sd1[r * 64 + m] * Wd2[m * 24 + p];
        out[(size_t)(b0 + r) * 24 + p] = s;
    }
}

extern "C" void kernel_launch(void* const* d_in, const int* in_sizes, int n_in,
                              void* d_out, int out_size) {
    const float* x   = (const float*)d_in[0];
    const float* W1  = (const float*)d_in[1];
    const float* U1w = (const float*)d_in[2];
    const float* b1  = (const float*)d_in[3];
    const float* W2  = (const float*)d_in[4];
    const float* U2w = (const float*)d_in[5];
    const float* b2  = (const float*)d_in[6];
    // d_in[7..10] = Wq, bq, Wk, bk: dead (softmax over seq-len 1 == 1)
    const float* Wv  = (const float*)d_in[11];
    const float* bv  = (const float*)d_in[12];
    const float* Wo  = (const float*)d_in[13];
    const float* bo  = (const float*)d_in[14];
    const float* Wd1 = (const float*)d_in[15];
    const float* bd1 = (const float*)d_in[16];
    const float* Wd2 = (const float*)d_in[17];
    const float* bd2 = (const float*)d_in[18];

    size_t smem = SMEM_FLOATS * sizeof(float);   // 169472 B
    cudaFuncSetAttribute(lstm_fused_kernel,
                         cudaFuncAttributeMaxDynamicSharedMemorySize, (int)smem);
    lstm_fused_kernel<<<CTAS, THREADS, smem>>>(
        x, W1, U1w, b1, W2, U2w, b2, Wv, bv, Wo, bo, Wd1, bd1, Wd2, bd2,
        (float*)d_out);
}